// round 14
// baseline (speedup 1.0000x reference)
#include <cuda_runtime.h>
#include <cuda_bf16.h>

#define BATCH   8
#define CH      512
#define SEQ     1024
#define NH      8
#define HD      64
#define QKV_DIM 1536
#define NTOK    (BATCH * SEQ)     // 8192
#define NBH     (BATCH * NH)      // 64

typedef unsigned long long ull;
typedef unsigned int u32;

__device__ __forceinline__ u32 smem_u32(const void* p) {
    u32 a;
    asm("{ .reg .u64 t; cvta.to.shared.u64 t, %1; cvt.u32.u64 %0, t; }" : "=r"(a) : "l"(p));
    return a;
}

// ---------------- warp MMA helpers (baseline PTX, sm_80+) ----------------
__device__ __forceinline__ void ldmx4(u32 addr, u32* r) {
    asm volatile("ldmatrix.sync.aligned.m8n8.x4.shared.b16 {%0,%1,%2,%3}, [%4];"
                 : "=r"(r[0]), "=r"(r[1]), "=r"(r[2]), "=r"(r[3]) : "r"(addr));
}
__device__ __forceinline__ void ldmx2(u32 addr, u32* r) {
    asm volatile("ldmatrix.sync.aligned.m8n8.x2.shared.b16 {%0,%1}, [%2];"
                 : "=r"(r[0]), "=r"(r[1]) : "r"(addr));
}
__device__ __forceinline__ void mma_bf16(float* d, const u32* a, const u32* b) {
    asm volatile("mma.sync.aligned.m16n8k16.row.col.f32.bf16.bf16.f32 "
                 "{%0,%1,%2,%3}, {%4,%5,%6,%7}, {%8,%9}, {%0,%1,%2,%3};"
                 : "+f"(d[0]), "+f"(d[1]), "+f"(d[2]), "+f"(d[3])
                 : "r"(a[0]), "r"(a[1]), "r"(a[2]), "r"(a[3]), "r"(b[0]), "r"(b[1]));
}
// ---------------- cp.async helpers ----------------
__device__ __forceinline__ void cpa16(u32 dst, const void* src) {
    asm volatile("cp.async.cg.shared.global [%0], [%1], 16;" :: "r"(dst), "l"(src));
}
__device__ __forceinline__ void cp_commit() {
    asm volatile("cp.async.commit_group;" ::: "memory");
}
template <int N>
__device__ __forceinline__ void cp_wait() {
    asm volatile("cp.async.wait_group %0;" :: "n"(N) : "memory");
}

// ---------------- global scratch ----------------
__device__ __nv_bfloat16 g_xT_hi[NTOK * CH], g_xT_lo[NTOK * CH];
__device__ __nv_bfloat16 g_wq_hi[QKV_DIM * CH], g_wq_lo[QKV_DIM * CH];
__device__ __nv_bfloat16 g_wp_hi[CH * CH],      g_wp_lo[CH * CH];
__device__ __nv_bfloat16 g_at_hi[NTOK * CH],    g_at_lo[NTOK * CH];
__device__ __nv_bfloat16 g_q_hi[NBH * SEQ * HD], g_q_lo[NBH * SEQ * HD];   // [bh][n][d]
__device__ __nv_bfloat16 g_k_hi[NBH * SEQ * HD], g_k_lo[NBH * SEQ * HD];   // [bh][n][d]
__device__ __nv_bfloat16 g_vt_hi[NBH * HD * SEQ], g_vt_lo[NBH * HD * SEQ]; // [bh][d][n]
__device__ float g_S[(size_t)NBH * SEQ * SEQ];
__device__ __nv_bfloat16 g_p_hi[(size_t)NBH * SEQ * SEQ];
__device__ __nv_bfloat16 g_p_lo[(size_t)NBH * SEQ * SEQ];

// ---------------- split store helpers ----------------
__device__ __forceinline__ void store_split2(__nv_bfloat16* hi, __nv_bfloat16* lo,
                                             size_t idx, float va, float vb)
{
    __nv_bfloat16 ha = __float2bfloat16(va), hb = __float2bfloat16(vb);
    __nv_bfloat162 hv; hv.x = ha; hv.y = hb;
    __nv_bfloat162 lv;
    lv.x = __float2bfloat16(va - __bfloat162float(ha));
    lv.y = __float2bfloat16(vb - __bfloat162float(hb));
    *(__nv_bfloat162*)(hi + idx) = hv;
    *(__nv_bfloat162*)(lo + idx) = lv;
}
__device__ __forceinline__ void store_split1(__nv_bfloat16* hi, __nv_bfloat16* lo,
                                             size_t idx, float v)
{
    __nv_bfloat16 h = __float2bfloat16(v);
    hi[idx] = h;
    lo[idx] = __float2bfloat16(v - __bfloat162float(h));
}

// qkv epilogue dispatch: token t, feature pair (j, j+1) -> q/k/vt splits
__device__ __forceinline__ void qkv_store(int t, int j, float va, float vb)
{
    const int b = t >> 10, n = t & 1023;
    if (j < 1024) {
        const int jj = j & 511;
        const int bh = b * 8 + (jj >> 6);
        const int d  = jj & 63;
        const size_t idx = ((size_t)bh << 16) + ((size_t)n << 6) + d;
        if (j < 512) store_split2(g_q_hi, g_q_lo, idx, va, vb);
        else         store_split2(g_k_hi, g_k_lo, idx, va, vb);
    } else {
        const int jj = j - 1024;
        const int bh = b * 8 + (jj >> 6);
        const int d  = jj & 63;
        const size_t idx = ((size_t)bh << 16) + ((size_t)d << 10) + n;
        store_split1(g_vt_hi, g_vt_lo, idx, va);
        store_split1(g_vt_hi, g_vt_lo, idx + 1024, vb);
    }
}

// ---------------- weight split-convert ----------------
__global__ void conv_split(int which, const float* __restrict__ src, int n)
{
    int i = blockIdx.x * 256 + threadIdx.x;
    if (i >= n) return;
    __nv_bfloat16 *hi = which ? g_wp_hi : g_wq_hi;
    __nv_bfloat16 *lo = which ? g_wp_lo : g_wq_lo;
    float v = src[i];
    __nv_bfloat16 h = __float2bfloat16(v);
    hi[i] = h;
    lo[i] = __float2bfloat16(v - __bfloat162float(h));
}

// ---------------- transpose-convert x[b][c][n] -> xT[(b,n)][c] hi/lo ----------------
__global__ void convT_x(const float* __restrict__ x)
{
    __shared__ float t[32][33];
    const int b  = blockIdx.z;
    const int n0 = blockIdx.x * 32;
    const int c0 = blockIdx.y * 32;
    const int tx = threadIdx.x, ty = threadIdx.y;
    #pragma unroll
    for (int i = 0; i < 4; i++)
        t[ty + i * 8][tx] = x[((size_t)b * CH + c0 + ty + i * 8) * SEQ + n0 + tx];
    __syncthreads();
    #pragma unroll
    for (int i = 0; i < 4; i++) {
        float v = t[tx][ty + i * 8];
        size_t idx = ((size_t)b * SEQ + n0 + ty + i * 8) * CH + c0 + tx;
        __nv_bfloat16 h = __float2bfloat16(v);
        g_xT_hi[idx] = h;
        g_xT_lo[idx] = __float2bfloat16(v - __bfloat162float(h));
    }
}

#define KST 40            // smem row stride (bf16) for 32-wide K-chunks
#define ARR_B 10240       // bytes per 128xKST bf16 array
#define BUF_B 40960       // 4 arrays per buffer
#define NSTAGE 4

extern __shared__ unsigned char dynsmem[];

// ---------------------------------------------------------------------------
// Main GEMMs: bf16x3 split mma.sync, 4-stage cp.async ring.
// 512 threads, 16 warps, 32x32 warp tiles (4x4 warp grid) for latency hiding.
// MODE 0: A=xT (m=tok), B=Wqkv (n=j)  -> epilogue writes q/k/vt splits directly
// MODE 1: A=Wp (m=ch),  B=att (n=tok) -> epilogue writes final output (NCHW)
// ---------------------------------------------------------------------------
template <int MODE>
__global__ void __launch_bounds__(512) gemm_mma(const float* __restrict__ bias,
                                                float* __restrict__ outp)
{
    constexpr int KDIM = 512;
    constexpr int NCHK = KDIM / 32;       // 16
    const int n0  = blockIdx.x * 128;
    const int m0  = blockIdx.y * 128;
    const int tid = threadIdx.x;
    const int w   = tid >> 5;
    const int lane = tid & 31;
    const int mw = (w & 3) * 32;          // 4-way m split
    const int nw = (w >> 2) * 32;         // 4-way n split

    const __nv_bfloat16 *Ahi, *Alo, *Bhi, *Blo;
    if (MODE == 0) { Ahi = g_xT_hi; Alo = g_xT_lo; Bhi = g_wq_hi; Blo = g_wq_lo; }
    else           { Ahi = g_wp_hi; Alo = g_wp_lo; Bhi = g_at_hi; Blo = g_at_lo; }

    const u32 sb = smem_u32(dynsmem);

    float acc[2][4][4];
    #pragma unroll
    for (int mf = 0; mf < 2; mf++)
        #pragma unroll
        for (int nf = 0; nf < 4; nf++)
            #pragma unroll
            for (int e = 0; e < 4; e++) acc[mf][nf][e] = 0.f;

    const u32 aOff = (u32)((mw + (lane & 15)) * (KST * 2) + (lane >> 4) * 16);
    const u32 bOff = (u32)((nw + (lane & 7)) * (KST * 2) + ((lane >> 3) & 1) * 16);

    // loader: 512 threads = one array sweep (128 rows x 4 col-groups)
    const int lrow = tid >> 2, lcc = tid & 3;

    auto issue = [&](int kc) {
        const int k0 = kc * 32;
        const u32 base = sb + (kc & 3) * BUF_B;
        size_t srcA = (size_t)(m0 + lrow) * KDIM + k0 + lcc * 8;
        size_t srcB = (size_t)(n0 + lrow) * KDIM + k0 + lcc * 8;
        u32 d = base + (u32)(2 * (lrow * KST + lcc * 8));
        cpa16(d,             Ahi + srcA);
        cpa16(d + ARR_B,     Alo + srcA);
        cpa16(d + 2 * ARR_B, Bhi + srcB);
        cpa16(d + 3 * ARR_B, Blo + srcB);
        cp_commit();
    };

    issue(0); issue(1); issue(2);
    for (int kc = 0; kc < NCHK; kc++) {
        cp_wait<2>();
        __syncthreads();

        const u32 base = sb + (kc & 3) * BUF_B;
        #pragma unroll
        for (int ks = 0; ks < 2; ks++) {
            u32 ahi[2][4], alo[2][4];
            #pragma unroll
            for (int mf = 0; mf < 2; mf++) {
                ldmx4(base + aOff + mf * (16 * KST * 2) + ks * 32, ahi[mf]);
                ldmx4(base + ARR_B + aOff + mf * (16 * KST * 2) + ks * 32, alo[mf]);
            }
            #pragma unroll
            for (int nf = 0; nf < 4; nf++) {
                u32 bh2[2], bl2[2];
                ldmx2(base + 2 * ARR_B + bOff + nf * (8 * KST * 2) + ks * 32, bh2);
                ldmx2(base + 3 * ARR_B + bOff + nf * (8 * KST * 2) + ks * 32, bl2);
                #pragma unroll
                for (int mf = 0; mf < 2; mf++) {
                    mma_bf16(acc[mf][nf], ahi[mf], bh2);
                    mma_bf16(acc[mf][nf], ahi[mf], bl2);
                    mma_bf16(acc[mf][nf], alo[mf], bh2);
                }
            }
        }
        if (kc + 3 < NCHK) issue(kc + 3);
        else               cp_commit();
    }

    const int g  = lane >> 2;
    const int tg = lane & 3;
    #pragma unroll
    for (int mf = 0; mf < 2; mf++) {
        const int mA = m0 + mw + mf * 16 + g;
        const int mB = mA + 8;
        #pragma unroll
        for (int nf = 0; nf < 4; nf++) {
            const int nn = n0 + nw + nf * 8 + tg * 2;
            if (MODE == 0) {
                float2 bb = *(const float2*)&bias[nn];
                qkv_store(mA, nn, acc[mf][nf][0] + bb.x, acc[mf][nf][1] + bb.y);
                qkv_store(mB, nn, acc[mf][nf][2] + bb.x, acc[mf][nf][3] + bb.y);
            } else {
                const int bb_ = nn >> 10, np = nn & 1023;
                float biasA = bias[mA], biasB = bias[mB];
                float* ob = outp + (size_t)bb_ * CH * SEQ + np;
                *(float2*)&ob[(size_t)mA * SEQ] =
                    make_float2(acc[mf][nf][0] + biasA, acc[mf][nf][1] + biasA);
                *(float2*)&ob[(size_t)mB * SEQ] =
                    make_float2(acc[mf][nf][2] + biasB, acc[mf][nf][3] + biasB);
            }
        }
    }
}

// ---------------------------------------------------------------------------
// QK^T GEMM: whole K=64 loaded in ONE async group; no k-loop.
// ---------------------------------------------------------------------------
#define QKST  72
#define QARR  18432

__global__ void __launch_bounds__(256) gemm_qk()
{
    const int tId = blockIdx.x;
    const int bh  = blockIdx.y;
    int r = 0, accT = 0;
    while (accT + r + 1 <= tId) { accT += r + 1; r++; }
    const int c = tId - accT;

    const int tid = threadIdx.x;
    const int w   = tid >> 5;
    const int lane = tid & 31;
    const int mw = (w & 1) * 64;
    const int nw = (w >> 1) * 32;

    const __nv_bfloat16* Ahi = g_q_hi + (size_t)bh * SEQ * HD + (size_t)r * 128 * HD;
    const __nv_bfloat16* Alo = g_q_lo + (size_t)bh * SEQ * HD + (size_t)r * 128 * HD;
    const __nv_bfloat16* Bhi = g_k_hi + (size_t)bh * SEQ * HD + (size_t)c * 128 * HD;
    const __nv_bfloat16* Blo = g_k_lo + (size_t)bh * SEQ * HD + (size_t)c * 128 * HD;

    const u32 sb = smem_u32(dynsmem);

    #pragma unroll
    for (int u = 0; u < 4; u++) {
        int idx = u * 256 + tid;
        int row = idx >> 3, cc = idx & 7;
        size_t src = (size_t)row * HD + cc * 8;
        u32 d = sb + (u32)(row * (QKST * 2) + cc * 16);
        cpa16(d,            Ahi + src);
        cpa16(d + QARR,     Alo + src);
        cpa16(d + 2 * QARR, Bhi + src);
        cpa16(d + 3 * QARR, Blo + src);
    }
    cp_commit();

    float acc[4][4][4];
    #pragma unroll
    for (int mf = 0; mf < 4; mf++)
        #pragma unroll
        for (int nf = 0; nf < 4; nf++)
            #pragma unroll
            for (int e = 0; e < 4; e++) acc[mf][nf][e] = 0.f;

    const u32 aOff = (u32)((mw + (lane & 15)) * (QKST * 2) + (lane >> 4) * 16);
    const u32 bOff = (u32)((nw + (lane & 7)) * (QKST * 2) + ((lane >> 3) & 1) * 16);

    cp_wait<0>();
    __syncthreads();

    #pragma unroll
    for (int ks = 0; ks < 4; ks++) {
        u32 ahi[4][4], alo[4][4];
        #pragma unroll
        for (int mf = 0; mf < 4; mf++) {
            ldmx4(sb + aOff + mf * (16 * QKST * 2) + ks * 32, ahi[mf]);
            ldmx4(sb + QARR + aOff + mf * (16 * QKST * 2) + ks * 32, alo[mf]);
        }
        #pragma unroll
        for (int nf = 0; nf < 4; nf++) {
            u32 bh2[2], bl2[2];
            ldmx2(sb + 2 * QARR + bOff + nf * (8 * QKST * 2) + ks * 32, bh2);
            ldmx2(sb + 3 * QARR + bOff + nf * (8 * QKST * 2) + ks * 32, bl2);
            #pragma unroll
            for (int mf = 0; mf < 4; mf++) {
                mma_bf16(acc[mf][nf], ahi[mf], bh2);
                mma_bf16(acc[mf][nf], ahi[mf], bl2);
                mma_bf16(acc[mf][nf], alo[mf], bh2);
            }
        }
    }

    const float scale = 0.125f;
    float* Sb = g_S + ((size_t)bh << 20);
    const int g  = lane >> 2;
    const int tg = lane & 3;
    #pragma unroll
    for (int mf = 0; mf < 4; mf++) {
        const int mA = r * 128 + mw + mf * 16 + g;
        const int mB = mA + 8;
        #pragma unroll
        for (int nf = 0; nf < 4; nf++) {
            const int nn = c * 128 + nw + nf * 8 + tg * 2;
            *(float2*)&Sb[(size_t)mA * SEQ + nn] =
                make_float2(acc[mf][nf][0] * scale, acc[mf][nf][1] * scale);
            *(float2*)&Sb[(size_t)mB * SEQ + nn] =
                make_float2(acc[mf][nf][2] * scale, acc[mf][nf][3] * scale);
        }
    }
}

// ---------------------------------------------------------------------------
// Softmax: one warp per row.
// ---------------------------------------------------------------------------
__global__ void __launch_bounds__(256) softmax_rows()
{
    const int lane = threadIdx.x & 31;
    const int wrp  = threadIdx.x >> 5;
    const int row  = blockIdx.x * 8 + wrp;
    const int bh   = row >> 10;
    const int i    = row & 1023;
    const int r    = i >> 7;
    const int nIt  = (r + 1) * 4;

    const float* Srow = g_S + ((size_t)bh << 20) + (size_t)i * SEQ;
    float sv[32];
    #pragma unroll
    for (int it = 0; it < 32; it++) {
        int j = it * 32 + lane;
        sv[it] = (it < nIt && j <= i) ? Srow[j] : -1e30f;
    }
    float m = -1e30f;
    #pragma unroll
    for (int it = 0; it < 32; it++) m = fmaxf(m, sv[it]);
    #pragma unroll
    for (int off = 16; off; off >>= 1) m = fmaxf(m, __shfl_xor_sync(0xffffffff, m, off));
    float sum = 0.f;
    #pragma unroll
    for (int it = 0; it < 32; it++) {
        float e = __expf(sv[it] - m);
        sv[it] = e;
        sum += e;
    }
    #pragma unroll
    for (int off = 16; off; off >>= 1) sum += __shfl_xor_sync(0xffffffff, sum, off);
    const float inv = 1.f / sum;

    __nv_bfloat16* Ph = g_p_hi + ((size_t)bh << 20) + (size_t)i * SEQ;
    __nv_bfloat16* Pl = g_p_lo + ((size_t)bh << 20) + (size_t)i * SEQ;
    #pragma unroll
    for (int it = 0; it < 32; it++) {
        if (it < nIt) {
            int j = it * 32 + lane;
            float p = sv[it] * inv;
            __nv_bfloat16 h = __float2bfloat16(p);
            Ph[j] = h;
            Pl[j] = __float2bfloat16(p - __bfloat162float(h));
        }
    }
}

// ---------------------------------------------------------------------------
// PV GEMM: 4-stage cp.async ring; epilogue writes g_at hi/lo splits directly.
// ---------------------------------------------------------------------------
#define PVBUF 30720

__global__ void __launch_bounds__(256) gemm_pv()
{
    const int r  = blockIdx.x;
    const int bh = blockIdx.y;
    const int b = bh >> 3, h = bh & 7;
    const int tid = threadIdx.x;
    const int w   = tid >> 5;
    const int lane = tid & 31;
    const int mw = (w & 3) * 32;
    const int nw = (w >> 2) * 32;

    const __nv_bfloat16* Phi = g_p_hi + ((size_t)bh << 20) + (size_t)r * 128 * SEQ;
    const __nv_bfloat16* Plo = g_p_lo + ((size_t)bh << 20) + (size_t)r * 128 * SEQ;
    const __nv_bfloat16* Vhi = g_vt_hi + (size_t)bh * HD * SEQ;
    const __nv_bfloat16* Vlo = g_vt_lo + (size_t)bh * HD * SEQ;

    const u32 sb = smem_u32(dynsmem);

    float acc[2][4][4];
    #pragma unroll
    for (int mf = 0; mf < 2; mf++)
        #pragma unroll
        for (int nf = 0; nf < 4; nf++)
            #pragma unroll
            for (int e = 0; e < 4; e++) acc[mf][nf][e] = 0.f;

    const u32 aOff = (u32)((mw + (lane & 15)) * (KST * 2) + (lane >> 4) * 16);
    const u32 bOff = (u32)((nw + (lane & 7)) * (KST * 2) + ((lane >> 3) & 1) * 16);

    const int prow0 = tid >> 2, pcc0 = tid & 3;
    const int prow1 = prow0 + 64;
    const int vrow  = tid >> 2, vcc = tid & 3;

    auto issue = [&](int kc) {
        const int k0 = kc * 32;
        const u32 base = sb + (kc & 3) * PVBUF;
        {
            size_t src = (size_t)prow0 * SEQ + k0 + pcc0 * 8;
            u32 d = base + (u32)(2 * (prow0 * KST + pcc0 * 8));
            cpa16(d,         Phi + src);
            cpa16(d + ARR_B, Plo + src);
        }
        {
            size_t src = (size_t)prow1 * SEQ + k0 + pcc0 * 8;
            u32 d = base + (u32)(2 * (prow1 * KST + pcc0 * 8));
            cpa16(d,         Phi + src);
            cpa16(d + ARR_B, Plo + src);
        }
        {
            size_t src = (size_t)vrow * SEQ + k0 + vcc * 8;
            u32 d = base + 2 * ARR_B + (u32)(2 * (vrow * KST + vcc * 8));
            cpa16(d,        Vhi + src);
            cpa16(d + 5120, Vlo + src);
        }
        cp_commit();
    };

    const int nch = (r + 1) * 4;
    issue(0); issue(1); issue(2);
    for (int kc = 0; kc < nch; kc++) {
        cp_wait<2>();
        __syncthreads();

        const u32 base = sb + (kc & 3) * PVBUF;
        #pragma unroll
        for (int ks = 0; ks < 2; ks++) {
            u32 ahi[2][4], alo[2][4];
            #pragma unroll
            for (int mf = 0; mf < 2; mf++) {
                ldmx4(base + aOff + mf * (16 * KST * 2) + ks * 32, ahi[mf]);
                ldmx4(base + ARR_B + aOff + mf * (16 * KST * 2) + ks * 32, alo[mf]);
            }
            #pragma unroll
            for (int nf = 0; nf < 4; nf++) {
                u32 bh2[2], bl2[2];
                ldmx2(base + 2 * ARR_B + bOff + nf * (8 * KST * 2) + ks * 32, bh2);
                ldmx2(base + 2 * ARR_B + 5120 + bOff + nf * (8 * KST * 2) + ks * 32, bl2);
                #pragma unroll
                for (int mf = 0; mf < 2; mf++) {
                    mma_bf16(acc[mf][nf], ahi[mf], bh2);
                    mma_bf16(acc[mf][nf], ahi[mf], bl2);
                    mma_bf16(acc[mf][nf], alo[mf], bh2);
                }
            }
        }
        if (kc + 3 < nch) issue(kc + 3);
        else              cp_commit();
    }

    const int g  = lane >> 2;
    const int tg = lane & 3;
    #pragma unroll
    for (int mf = 0; mf < 2; mf++) {
        const int mA = r * 128 + mw + mf * 16 + g;
        const int mB = mA + 8;
        const size_t oA = ((size_t)(b * SEQ + mA)) * CH + h * HD;
        const size_t oB = ((size_t)(b * SEQ + mB)) * CH + h * HD;
        #pragma unroll
        for (int nf = 0; nf < 4; nf++) {
            const int nn = nw + nf * 8 + tg * 2;
            store_split2(g_at_hi, g_at_lo, oA + nn, acc[mf][nf][0], acc[mf][nf][1]);
            store_split2(g_at_hi, g_at_lo, oB + nn, acc[mf][nf][2], acc[mf][nf][3]);
        }
    }
}

// ---------------------------------------------------------------------------
extern "C" void kernel_launch(void* const* d_in, const int* in_sizes, int n_in,
                              void* d_out, int out_size)
{
    const float* x    = (const float*)d_in[0];
    const float* Wqkv = (const float*)d_in[1];
    const float* bqkv = (const float*)d_in[2];
    const float* Wp   = (const float*)d_in[3];
    const float* bp   = (const float*)d_in[4];
    float* out = (float*)d_out;
    (void)in_sizes; (void)n_in; (void)out_size;

    static int attr_done = 0;
    if (!attr_done) {
        cudaFuncSetAttribute(gemm_mma<0>, cudaFuncAttributeMaxDynamicSharedMemorySize, NSTAGE * BUF_B);
        cudaFuncSetAttribute(gemm_mma<1>, cudaFuncAttributeMaxDynamicSharedMemorySize, NSTAGE * BUF_B);
        cudaFuncSetAttribute(gemm_qk,     cudaFuncAttributeMaxDynamicSharedMemorySize, 4 * QARR);
        cudaFuncSetAttribute(gemm_pv,     cudaFuncAttributeMaxDynamicSharedMemorySize, NSTAGE * PVBUF);
        attr_done = 1;
    }

    conv_split<<<(QKV_DIM * CH + 255) / 256, 256>>>(0, Wqkv, QKV_DIM * CH);
    conv_split<<<(CH * CH + 255) / 256, 256>>>(1, Wp, CH * CH);
    convT_x<<<dim3(SEQ / 32, CH / 32, BATCH), dim3(32, 8)>>>(x);

    gemm_mma<0><<<dim3(QKV_DIM / 128, NTOK / 128), 512, NSTAGE * BUF_B>>>(bqkv, out);  // -> q/k/vt splits

    gemm_qk<<<dim3(36, NBH), 256, 4 * QARR>>>();                                       // -> g_S
    softmax_rows<<<(NBH * SEQ) / 8, 256>>>();                                          // -> g_p
    gemm_pv<<<dim3(SEQ / 128, NBH), 256, NSTAGE * PVBUF>>>();                          // -> g_at splits

    gemm_mma<1><<<dim3(NTOK / 128, CH / 128), 512, NSTAGE * BUF_B>>>(bp, out);         // -> out
}

// round 16
// speedup vs baseline: 1.2553x; 1.2553x over previous
#include <cuda_runtime.h>
#include <cuda_bf16.h>

#define BATCH   8
#define CH      512
#define SEQ     1024
#define NH      8
#define HD      64
#define QKV_DIM 1536
#define NTOK    (BATCH * SEQ)     // 8192
#define NBH     (BATCH * NH)      // 64

typedef unsigned long long ull;
typedef unsigned int u32;

__device__ __forceinline__ u32 smem_u32(const void* p) {
    u32 a;
    asm("{ .reg .u64 t; cvta.to.shared.u64 t, %1; cvt.u32.u64 %0, t; }" : "=r"(a) : "l"(p));
    return a;
}

// ---------------- warp MMA helpers (baseline PTX, sm_80+) ----------------
__device__ __forceinline__ void ldmx4(u32 addr, u32* r) {
    asm volatile("ldmatrix.sync.aligned.m8n8.x4.shared.b16 {%0,%1,%2,%3}, [%4];"
                 : "=r"(r[0]), "=r"(r[1]), "=r"(r[2]), "=r"(r[3]) : "r"(addr));
}
__device__ __forceinline__ void ldmx2(u32 addr, u32* r) {
    asm volatile("ldmatrix.sync.aligned.m8n8.x2.shared.b16 {%0,%1}, [%2];"
                 : "=r"(r[0]), "=r"(r[1]) : "r"(addr));
}
__device__ __forceinline__ void mma_bf16(float* d, const u32* a, const u32* b) {
    asm volatile("mma.sync.aligned.m16n8k16.row.col.f32.bf16.bf16.f32 "
                 "{%0,%1,%2,%3}, {%4,%5,%6,%7}, {%8,%9}, {%0,%1,%2,%3};"
                 : "+f"(d[0]), "+f"(d[1]), "+f"(d[2]), "+f"(d[3])
                 : "r"(a[0]), "r"(a[1]), "r"(a[2]), "r"(a[3]), "r"(b[0]), "r"(b[1]));
}
// ---------------- cp.async helpers ----------------
__device__ __forceinline__ void cpa16(u32 dst, const void* src) {
    asm volatile("cp.async.cg.shared.global [%0], [%1], 16;" :: "r"(dst), "l"(src));
}
__device__ __forceinline__ void cp_commit() {
    asm volatile("cp.async.commit_group;" ::: "memory");
}
template <int N>
__device__ __forceinline__ void cp_wait() {
    asm volatile("cp.async.wait_group %0;" :: "n"(N) : "memory");
}

// ---------------- global scratch ----------------
__device__ __nv_bfloat16 g_xT_hi[NTOK * CH], g_xT_lo[NTOK * CH];
__device__ __nv_bfloat16 g_wq_hi[QKV_DIM * CH], g_wq_lo[QKV_DIM * CH];
__device__ __nv_bfloat16 g_wp_hi[CH * CH],      g_wp_lo[CH * CH];
__device__ __nv_bfloat16 g_at_hi[NTOK * CH],    g_at_lo[NTOK * CH];
__device__ __nv_bfloat16 g_q_hi[NBH * SEQ * HD], g_q_lo[NBH * SEQ * HD];   // [bh][n][d] (pre-scaled)
__device__ __nv_bfloat16 g_k_hi[NBH * SEQ * HD], g_k_lo[NBH * SEQ * HD];   // [bh][n][d]
__device__ __nv_bfloat16 g_vt_hi[NBH * HD * SEQ], g_vt_lo[NBH * HD * SEQ]; // [bh][d][n]

// ---------------- split helpers ----------------
__device__ __forceinline__ void store_split2(__nv_bfloat16* hi, __nv_bfloat16* lo,
                                             size_t idx, float va, float vb)
{
    __nv_bfloat16 ha = __float2bfloat16(va), hb = __float2bfloat16(vb);
    __nv_bfloat162 hv; hv.x = ha; hv.y = hb;
    __nv_bfloat162 lv;
    lv.x = __float2bfloat16(va - __bfloat162float(ha));
    lv.y = __float2bfloat16(vb - __bfloat162float(hb));
    *(__nv_bfloat162*)(hi + idx) = hv;
    *(__nv_bfloat162*)(lo + idx) = lv;
}
__device__ __forceinline__ void store_split1(__nv_bfloat16* hi, __nv_bfloat16* lo,
                                             size_t idx, float v)
{
    __nv_bfloat16 h = __float2bfloat16(v);
    hi[idx] = h;
    lo[idx] = __float2bfloat16(v - __bfloat162float(h));
}
// pack pair (a,b) into bf16x2 hi-frag + residual lo-frag
__device__ __forceinline__ void split_pack(float a, float b, u32& hi, u32& lo)
{
    __nv_bfloat16 ha = __float2bfloat16(a), hb = __float2bfloat16(b);
    __nv_bfloat162 hv; hv.x = ha; hv.y = hb;
    __nv_bfloat162 lv;
    lv.x = __float2bfloat16(a - __bfloat162float(ha));
    lv.y = __float2bfloat16(b - __bfloat162float(hb));
    hi = *(u32*)&hv;
    lo = *(u32*)&lv;
}

// qkv epilogue dispatch: token t, feature pair (j, j+1) -> q/k/vt splits
// q is pre-scaled by HD^-0.5 so attention scores come out scaled.
__device__ __forceinline__ void qkv_store(int t, int j, float va, float vb)
{
    const int b = t >> 10, n = t & 1023;
    if (j < 1024) {
        const int jj = j & 511;
        const int bh = b * 8 + (jj >> 6);
        const int d  = jj & 63;
        const size_t idx = ((size_t)bh << 16) + ((size_t)n << 6) + d;
        if (j < 512) store_split2(g_q_hi, g_q_lo, idx, va * 0.125f, vb * 0.125f);
        else         store_split2(g_k_hi, g_k_lo, idx, va, vb);
    } else {
        const int jj = j - 1024;
        const int bh = b * 8 + (jj >> 6);
        const int d  = jj & 63;
        const size_t idx = ((size_t)bh << 16) + ((size_t)d << 10) + n;
        store_split1(g_vt_hi, g_vt_lo, idx, va);
        store_split1(g_vt_hi, g_vt_lo, idx + 1024, vb);
    }
}

// ---------------- weight split-convert ----------------
__global__ void conv_split(int which, const float* __restrict__ src, int n)
{
    int i = blockIdx.x * 256 + threadIdx.x;
    if (i >= n) return;
    __nv_bfloat16 *hi = which ? g_wp_hi : g_wq_hi;
    __nv_bfloat16 *lo = which ? g_wp_lo : g_wq_lo;
    float v = src[i];
    __nv_bfloat16 h = __float2bfloat16(v);
    hi[i] = h;
    lo[i] = __float2bfloat16(v - __bfloat162float(h));
}

// ---------------- transpose-convert x[b][c][n] -> xT[(b,n)][c] hi/lo ----------------
__global__ void convT_x(const float* __restrict__ x)
{
    __shared__ float t[32][33];
    const int b  = blockIdx.z;
    const int n0 = blockIdx.x * 32;
    const int c0 = blockIdx.y * 32;
    const int tx = threadIdx.x, ty = threadIdx.y;
    #pragma unroll
    for (int i = 0; i < 4; i++)
        t[ty + i * 8][tx] = x[((size_t)b * CH + c0 + ty + i * 8) * SEQ + n0 + tx];
    __syncthreads();
    #pragma unroll
    for (int i = 0; i < 4; i++) {
        float v = t[tx][ty + i * 8];
        size_t idx = ((size_t)b * SEQ + n0 + ty + i * 8) * CH + c0 + tx;
        __nv_bfloat16 h = __float2bfloat16(v);
        g_xT_hi[idx] = h;
        g_xT_lo[idx] = __float2bfloat16(v - __bfloat162float(h));
    }
}

#define KST 40            // smem row stride (bf16) for 32-wide K-chunks (projection GEMMs)
#define ARR_B 10240       // bytes per 128xKST bf16 array
#define BUF_B 40960       // 4 arrays per buffer
#define NSTAGE 4

extern __shared__ unsigned char dynsmem[];

// ---------------------------------------------------------------------------
// Projection GEMMs: bf16x3 split, 4-stage cp.async ring, 512 threads.
// ---------------------------------------------------------------------------
template <int MODE>
__global__ void __launch_bounds__(512) gemm_mma(const float* __restrict__ bias,
                                                float* __restrict__ outp)
{
    constexpr int KDIM = 512;
    constexpr int NCHK = KDIM / 32;
    const int n0  = blockIdx.x * 128;
    const int m0  = blockIdx.y * 128;
    const int tid = threadIdx.x;
    const int w   = tid >> 5;
    const int lane = tid & 31;
    const int mw = (w & 3) * 32;
    const int nw = (w >> 2) * 32;

    const __nv_bfloat16 *Ahi, *Alo, *Bhi, *Blo;
    if (MODE == 0) { Ahi = g_xT_hi; Alo = g_xT_lo; Bhi = g_wq_hi; Blo = g_wq_lo; }
    else           { Ahi = g_wp_hi; Alo = g_wp_lo; Bhi = g_at_hi; Blo = g_at_lo; }

    const u32 sb = smem_u32(dynsmem);

    float acc[2][4][4];
    #pragma unroll
    for (int mf = 0; mf < 2; mf++)
        #pragma unroll
        for (int nf = 0; nf < 4; nf++)
            #pragma unroll
            for (int e = 0; e < 4; e++) acc[mf][nf][e] = 0.f;

    const u32 aOff = (u32)((mw + (lane & 15)) * (KST * 2) + (lane >> 4) * 16);
    const u32 bOff = (u32)((nw + (lane & 7)) * (KST * 2) + ((lane >> 3) & 1) * 16);

    const int lrow = tid >> 2, lcc = tid & 3;

    auto issue = [&](int kc) {
        const int k0 = kc * 32;
        const u32 base = sb + (kc & 3) * BUF_B;
        size_t srcA = (size_t)(m0 + lrow) * KDIM + k0 + lcc * 8;
        size_t srcB = (size_t)(n0 + lrow) * KDIM + k0 + lcc * 8;
        u32 d = base + (u32)(2 * (lrow * KST + lcc * 8));
        cpa16(d,             Ahi + srcA);
        cpa16(d + ARR_B,     Alo + srcA);
        cpa16(d + 2 * ARR_B, Bhi + srcB);
        cpa16(d + 3 * ARR_B, Blo + srcB);
        cp_commit();
    };

    issue(0); issue(1); issue(2);
    for (int kc = 0; kc < NCHK; kc++) {
        cp_wait<2>();
        __syncthreads();

        const u32 base = sb + (kc & 3) * BUF_B;
        #pragma unroll
        for (int ks = 0; ks < 2; ks++) {
            u32 ahi[2][4], alo[2][4];
            #pragma unroll
            for (int mf = 0; mf < 2; mf++) {
                ldmx4(base + aOff + mf * (16 * KST * 2) + ks * 32, ahi[mf]);
                ldmx4(base + ARR_B + aOff + mf * (16 * KST * 2) + ks * 32, alo[mf]);
            }
            #pragma unroll
            for (int nf = 0; nf < 4; nf++) {
                u32 bh2[2], bl2[2];
                ldmx2(base + 2 * ARR_B + bOff + nf * (8 * KST * 2) + ks * 32, bh2);
                ldmx2(base + 3 * ARR_B + bOff + nf * (8 * KST * 2) + ks * 32, bl2);
                #pragma unroll
                for (int mf = 0; mf < 2; mf++) {
                    mma_bf16(acc[mf][nf], ahi[mf], bh2);
                    mma_bf16(acc[mf][nf], ahi[mf], bl2);
                    mma_bf16(acc[mf][nf], alo[mf], bh2);
                }
            }
        }
        if (kc + 3 < NCHK) issue(kc + 3);
        else               cp_commit();
    }

    const int g  = lane >> 2;
    const int tg = lane & 3;
    #pragma unroll
    for (int mf = 0; mf < 2; mf++) {
        const int mA = m0 + mw + mf * 16 + g;
        const int mB = mA + 8;
        #pragma unroll
        for (int nf = 0; nf < 4; nf++) {
            const int nn = n0 + nw + nf * 8 + tg * 2;
            if (MODE == 0) {
                float2 bb = *(const float2*)&bias[nn];
                qkv_store(mA, nn, acc[mf][nf][0] + bb.x, acc[mf][nf][1] + bb.y);
                qkv_store(mB, nn, acc[mf][nf][2] + bb.x, acc[mf][nf][3] + bb.y);
            } else {
                const int bb_ = nn >> 10, np = nn & 1023;
                float biasA = bias[mA], biasB = bias[mB];
                float* ob = outp + (size_t)bb_ * CH * SEQ + np;
                *(float2*)&ob[(size_t)mA * SEQ] =
                    make_float2(acc[mf][nf][0] + biasA, acc[mf][nf][1] + biasA);
                *(float2*)&ob[(size_t)mB * SEQ] =
                    make_float2(acc[mf][nf][2] + biasB, acc[mf][nf][3] + biasB);
            }
        }
    }
}

// ---------------------------------------------------------------------------
// Fused flash attention. Q/K rows are 64 bf16 = 128 B -> row stride 144 B
// (QST2; the R15 bug was using the 80-B projection stride here).
// grid (8 q-blocks reversed, 64 bh), 256 thr, 8 warps x 16 q-rows.
// SMEM: Q 2x18432 + 2 stages x (K 2x18432 + Vt 2x17408) = 180224 B.
// ---------------------------------------------------------------------------
#define QST2  144                      // Q/K row stride bytes (72 bf16)
#define QARR  18432                    // 128*144
#define VST2  272                      // Vt row stride bytes (136 bf16)
#define VARR  17408                    // 64*272
#define STGSZ (2 * QARR + 2 * VARR)    // 71680
#define SOFF  (2 * QARR)               // stages start after Q (36864)

__global__ void __launch_bounds__(256) attn_fused()
{
    const int r   = 7 - (int)blockIdx.x;   // heavy q-blocks first
    const int bh  = blockIdx.y;
    const int b   = bh >> 3, h = bh & 7;
    const int tid = threadIdx.x;
    const int w   = tid >> 5;
    const int lane = tid & 31;
    const int g  = lane >> 2, tg = lane & 3;

    const __nv_bfloat16* Qhi = g_q_hi + ((size_t)bh << 16) + (size_t)r * 128 * HD;
    const __nv_bfloat16* Qlo = g_q_lo + ((size_t)bh << 16) + (size_t)r * 128 * HD;
    const __nv_bfloat16* Khi = g_k_hi + ((size_t)bh << 16);
    const __nv_bfloat16* Klo = g_k_lo + ((size_t)bh << 16);
    const __nv_bfloat16* Vhi = g_vt_hi + ((size_t)bh << 16);
    const __nv_bfloat16* Vlo = g_vt_lo + ((size_t)bh << 16);

    const u32 sb = smem_u32(dynsmem);

    // ---- load Q block (hi+lo): 128 rows x 8 x 16B chunks ----
    {
        #pragma unroll
        for (int u = 0; u < 4; u++) {
            int idx = u * 256 + tid;
            int row = idx >> 3, c8 = idx & 7;
            size_t src = (size_t)row * HD + c8 * 8;
            u32 d = sb + (u32)(row * QST2 + c8 * 16);
            cpa16(d,        Qhi + src);
            cpa16(d + QARR, Qlo + src);
        }
        cp_commit();
    }

    // ---- stage issue: K block c + Vt slice c ----
    auto issueKV = [&](int c) {
        const u32 base = sb + SOFF + (c & 1) * STGSZ;
        #pragma unroll
        for (int u = 0; u < 4; u++) {
            int idx = u * 256 + tid;
            {   // K: 128 rows x 8 chunks
                int row = idx >> 3, c8 = idx & 7;
                size_t src = (size_t)(c * 128 + row) * HD + c8 * 8;
                u32 d = base + (u32)(row * QST2 + c8 * 16);
                cpa16(d,        Khi + src);
                cpa16(d + QARR, Klo + src);
            }
            {   // Vt: 64 rows x 16 chunks
                int row = idx >> 4, c16 = idx & 15;
                size_t src = (size_t)row * SEQ + c * 128 + c16 * 8;
                u32 d = base + 2 * QARR + (u32)(row * VST2 + c16 * 16);
                cpa16(d,        Vhi + src);
                cpa16(d + VARR, Vlo + src);
            }
        }
        cp_commit();
    };

    issueKV(0);
    cp_wait<1>();       // Q group complete
    __syncthreads();

    // ---- Q fragments to registers ----
    u32 qh[4][4], ql[4][4];
    {
        const u32 qa = sb + (u32)((w * 16 + (lane & 15)) * QST2 + (lane >> 4) * 16);
        #pragma unroll
        for (int ks = 0; ks < 4; ks++) {
            ldmx4(qa + ks * 32,        qh[ks]);
            ldmx4(qa + QARR + ks * 32, ql[ks]);
        }
    }

    if (r >= 1) issueKV(1);

    float o[8][4];
    #pragma unroll
    for (int nt = 0; nt < 8; nt++)
        #pragma unroll
        for (int e = 0; e < 4; e++) o[nt][e] = 0.f;
    float m0 = -1e30f, m1 = -1e30f, l0 = 0.f, l1 = 0.f;

    for (int c = 0; c <= r; c++) {
        if (c == r) cp_wait<0>(); else cp_wait<1>();
        __syncthreads();
        const u32 base = sb + SOFF + (c & 1) * STGSZ;

        // ---- S = Q K^T (3-product split), per-warp 16x128 tile ----
        float s[16][4];
        #pragma unroll
        for (int nt = 0; nt < 16; nt++)
            #pragma unroll
            for (int e = 0; e < 4; e++) s[nt][e] = 0.f;

        #pragma unroll
        for (int ks = 0; ks < 4; ks++) {
            #pragma unroll
            for (int nt = 0; nt < 16; nt++) {
                u32 kh2[2], kl2[2];
                u32 ka = base + (u32)((nt * 8 + (lane & 7)) * QST2 +
                                      ((lane >> 3) & 1) * 16 + ks * 32);
                ldmx2(ka,        kh2);
                ldmx2(ka + QARR, kl2);
                mma_bf16(s[nt], qh[ks], kh2);
                mma_bf16(s[nt], qh[ks], kl2);
                mma_bf16(s[nt], ql[ks], kh2);
            }
        }

        // ---- causal mask (diagonal block only) ----
        if (c == r) {
            const int i0 = w * 16 + g;       // row of e=0,1
            const int i1 = i0 + 8;           // row of e=2,3
            #pragma unroll
            for (int nt = 0; nt < 16; nt++) {
                const int j0 = nt * 8 + tg * 2;
                if (j0     > i0) s[nt][0] = -1e30f;
                if (j0 + 1 > i0) s[nt][1] = -1e30f;
                if (j0     > i1) s[nt][2] = -1e30f;
                if (j0 + 1 > i1) s[nt][3] = -1e30f;
            }
        }

        // ---- online softmax ----
        float mb0 = -1e30f, mb1 = -1e30f;
        #pragma unroll
        for (int nt = 0; nt < 16; nt++) {
            mb0 = fmaxf(mb0, fmaxf(s[nt][0], s[nt][1]));
            mb1 = fmaxf(mb1, fmaxf(s[nt][2], s[nt][3]));
        }
        mb0 = fmaxf(mb0, __shfl_xor_sync(0xffffffff, mb0, 1));
        mb0 = fmaxf(mb0, __shfl_xor_sync(0xffffffff, mb0, 2));
        mb1 = fmaxf(mb1, __shfl_xor_sync(0xffffffff, mb1, 1));
        mb1 = fmaxf(mb1, __shfl_xor_sync(0xffffffff, mb1, 2));

        const float mn0 = fmaxf(m0, mb0);
        const float mn1 = fmaxf(m1, mb1);
        const float a0 = __expf(m0 - mn0);
        const float a1 = __expf(m1 - mn1);
        l0 *= a0; l1 *= a1;
        #pragma unroll
        for (int nt = 0; nt < 8; nt++) {
            o[nt][0] *= a0; o[nt][1] *= a0;
            o[nt][2] *= a1; o[nt][3] *= a1;
        }
        float s0 = 0.f, s1 = 0.f;
        #pragma unroll
        for (int nt = 0; nt < 16; nt++) {
            s[nt][0] = __expf(s[nt][0] - mn0); s0 += s[nt][0];
            s[nt][1] = __expf(s[nt][1] - mn0); s0 += s[nt][1];
            s[nt][2] = __expf(s[nt][2] - mn1); s1 += s[nt][2];
            s[nt][3] = __expf(s[nt][3] - mn1); s1 += s[nt][3];
        }
        s0 += __shfl_xor_sync(0xffffffff, s0, 1);
        s0 += __shfl_xor_sync(0xffffffff, s0, 2);
        s1 += __shfl_xor_sync(0xffffffff, s1, 1);
        s1 += __shfl_xor_sync(0xffffffff, s1, 2);
        l0 += s0; l1 += s1;
        m0 = mn0; m1 = mn1;

        // ---- O += P V : P frags straight from registers ----
        #pragma unroll
        for (int kk = 0; kk < 8; kk++) {
            u32 ah[4], al[4];
            split_pack(s[2*kk][0],   s[2*kk][1],   ah[0], al[0]);
            split_pack(s[2*kk][2],   s[2*kk][3],   ah[1], al[1]);
            split_pack(s[2*kk+1][0], s[2*kk+1][1], ah[2], al[2]);
            split_pack(s[2*kk+1][2], s[2*kk+1][3], ah[3], al[3]);
            #pragma unroll
            for (int nt = 0; nt < 8; nt++) {
                u32 vh2[2], vl2[2];
                u32 va = base + 2 * QARR +
                         (u32)((nt * 8 + (lane & 7)) * VST2 +
                               ((lane >> 3) & 1) * 16 + kk * 32);
                ldmx2(va,        vh2);
                ldmx2(va + VARR, vl2);
                mma_bf16(o[nt], ah, vh2);
                mma_bf16(o[nt], ah, vl2);
                mma_bf16(o[nt], al, vh2);
            }
        }

        __syncthreads();                 // all warps done with stage c
        if (c + 2 <= r) issueKV(c + 2);  // refill the buffer just freed
    }

    // ---- epilogue: O / l -> g_at splits ----
    const float inv0 = 1.f / l0;
    const float inv1 = 1.f / l1;
    const int iA = r * 128 + w * 16 + g;
    const int iB = iA + 8;
    const size_t oA = ((size_t)(b * SEQ + iA)) * CH + h * HD;
    const size_t oB = ((size_t)(b * SEQ + iB)) * CH + h * HD;
    #pragma unroll
    for (int nt = 0; nt < 8; nt++) {
        const int dd = nt * 8 + tg * 2;
        store_split2(g_at_hi, g_at_lo, oA + dd, o[nt][0] * inv0, o[nt][1] * inv0);
        store_split2(g_at_hi, g_at_lo, oB + dd, o[nt][2] * inv1, o[nt][3] * inv1);
    }
}

// ---------------------------------------------------------------------------
extern "C" void kernel_launch(void* const* d_in, const int* in_sizes, int n_in,
                              void* d_out, int out_size)
{
    const float* x    = (const float*)d_in[0];
    const float* Wqkv = (const float*)d_in[1];
    const float* bqkv = (const float*)d_in[2];
    const float* Wp   = (const float*)d_in[3];
    const float* bp   = (const float*)d_in[4];
    float* out = (float*)d_out;
    (void)in_sizes; (void)n_in; (void)out_size;

    static int attr_done = 0;
    if (!attr_done) {
        cudaFuncSetAttribute(gemm_mma<0>, cudaFuncAttributeMaxDynamicSharedMemorySize, NSTAGE * BUF_B);
        cudaFuncSetAttribute(gemm_mma<1>, cudaFuncAttributeMaxDynamicSharedMemorySize, NSTAGE * BUF_B);
        cudaFuncSetAttribute(attn_fused,  cudaFuncAttributeMaxDynamicSharedMemorySize, SOFF + 2 * STGSZ);
        attr_done = 1;
    }

    conv_split<<<(QKV_DIM * CH + 255) / 256, 256>>>(0, Wqkv, QKV_DIM * CH);
    conv_split<<<(CH * CH + 255) / 256, 256>>>(1, Wp, CH * CH);
    convT_x<<<dim3(SEQ / 32, CH / 32, BATCH), dim3(32, 8)>>>(x);

    gemm_mma<0><<<dim3(QKV_DIM / 128, NTOK / 128), 512, NSTAGE * BUF_B>>>(bqkv, out);  // -> q/k/vt splits

    attn_fused<<<dim3(8, NBH), 256, SOFF + 2 * STGSZ>>>();                             // -> g_at splits

    gemm_mma<1><<<dim3(NTOK / 128, CH / 128), 512, NSTAGE * BUF_B>>>(bp, out);         // -> out
}

// round 17
// speedup vs baseline: 1.4144x; 1.1268x over previous
#include <cuda_runtime.h>
#include <cuda_bf16.h>

#define BATCH   8
#define CH      512
#define SEQ     1024
#define NH      8
#define HD      64
#define QKV_DIM 1536
#define NTOK    (BATCH * SEQ)     // 8192
#define NBH     (BATCH * NH)      // 64

typedef unsigned long long ull;
typedef unsigned int u32;

__device__ __forceinline__ u32 smem_u32(const void* p) {
    u32 a;
    asm("{ .reg .u64 t; cvta.to.shared.u64 t, %1; cvt.u32.u64 %0, t; }" : "=r"(a) : "l"(p));
    return a;
}

// ---------------- warp MMA helpers (baseline PTX, sm_80+) ----------------
__device__ __forceinline__ void ldmx4(u32 addr, u32* r) {
    asm volatile("ldmatrix.sync.aligned.m8n8.x4.shared.b16 {%0,%1,%2,%3}, [%4];"
                 : "=r"(r[0]), "=r"(r[1]), "=r"(r[2]), "=r"(r[3]) : "r"(addr));
}
__device__ __forceinline__ void mma_bf16(float* d, const u32* a, const u32* b) {
    asm volatile("mma.sync.aligned.m16n8k16.row.col.f32.bf16.bf16.f32 "
                 "{%0,%1,%2,%3}, {%4,%5,%6,%7}, {%8,%9}, {%0,%1,%2,%3};"
                 : "+f"(d[0]), "+f"(d[1]), "+f"(d[2]), "+f"(d[3])
                 : "r"(a[0]), "r"(a[1]), "r"(a[2]), "r"(a[3]), "r"(b[0]), "r"(b[1]));
}
// ---------------- cp.async helpers ----------------
__device__ __forceinline__ void cpa16(u32 dst, const void* src) {
    asm volatile("cp.async.cg.shared.global [%0], [%1], 16;" :: "r"(dst), "l"(src));
}
__device__ __forceinline__ void cp_commit() {
    asm volatile("cp.async.commit_group;" ::: "memory");
}
template <int N>
__device__ __forceinline__ void cp_wait() {
    asm volatile("cp.async.wait_group %0;" :: "n"(N) : "memory");
}

// ---------------- global scratch ----------------
__device__ __nv_bfloat16 g_xT_hi[NTOK * CH], g_xT_lo[NTOK * CH];
__device__ __nv_bfloat16 g_wq_hi[QKV_DIM * CH], g_wq_lo[QKV_DIM * CH];
__device__ __nv_bfloat16 g_wp_hi[CH * CH],      g_wp_lo[CH * CH];
__device__ __nv_bfloat16 g_at_hi[NTOK * CH],    g_at_lo[NTOK * CH];
__device__ __nv_bfloat16 g_q_hi[NBH * SEQ * HD], g_q_lo[NBH * SEQ * HD];   // [bh][n][d] (pre-scaled)
__device__ __nv_bfloat16 g_k_hi[NBH * SEQ * HD], g_k_lo[NBH * SEQ * HD];   // [bh][n][d]
__device__ __nv_bfloat16 g_vt_hi[NBH * HD * SEQ], g_vt_lo[NBH * HD * SEQ]; // [bh][d][n]

// ---------------- split helpers ----------------
__device__ __forceinline__ void store_split2(__nv_bfloat16* hi, __nv_bfloat16* lo,
                                             size_t idx, float va, float vb)
{
    __nv_bfloat16 ha = __float2bfloat16(va), hb = __float2bfloat16(vb);
    __nv_bfloat162 hv; hv.x = ha; hv.y = hb;
    __nv_bfloat162 lv;
    lv.x = __float2bfloat16(va - __bfloat162float(ha));
    lv.y = __float2bfloat16(vb - __bfloat162float(hb));
    *(__nv_bfloat162*)(hi + idx) = hv;
    *(__nv_bfloat162*)(lo + idx) = lv;
}
__device__ __forceinline__ void store_split1(__nv_bfloat16* hi, __nv_bfloat16* lo,
                                             size_t idx, float v)
{
    __nv_bfloat16 h = __float2bfloat16(v);
    hi[idx] = h;
    lo[idx] = __float2bfloat16(v - __bfloat162float(h));
}
__device__ __forceinline__ void split_pack(float a, float b, u32& hi, u32& lo)
{
    __nv_bfloat16 ha = __float2bfloat16(a), hb = __float2bfloat16(b);
    __nv_bfloat162 hv; hv.x = ha; hv.y = hb;
    __nv_bfloat162 lv;
    lv.x = __float2bfloat16(a - __bfloat162float(ha));
    lv.y = __float2bfloat16(b - __bfloat162float(hb));
    hi = *(u32*)&hv;
    lo = *(u32*)&lv;
}

// qkv epilogue dispatch (q pre-scaled by HD^-0.5)
__device__ __forceinline__ void qkv_store(int t, int j, float va, float vb)
{
    const int b = t >> 10, n = t & 1023;
    if (j < 1024) {
        const int jj = j & 511;
        const int bh = b * 8 + (jj >> 6);
        const int d  = jj & 63;
        const size_t idx = ((size_t)bh << 16) + ((size_t)n << 6) + d;
        if (j < 512) store_split2(g_q_hi, g_q_lo, idx, va * 0.125f, vb * 0.125f);
        else         store_split2(g_k_hi, g_k_lo, idx, va, vb);
    } else {
        const int jj = j - 1024;
        const int bh = b * 8 + (jj >> 6);
        const int d  = jj & 63;
        const size_t idx = ((size_t)bh << 16) + ((size_t)d << 10) + n;
        store_split1(g_vt_hi, g_vt_lo, idx, va);
        store_split1(g_vt_hi, g_vt_lo, idx + 1024, vb);
    }
}

// ---------------- weight split-convert ----------------
__global__ void conv_split(int which, const float* __restrict__ src, int n)
{
    int i = blockIdx.x * 256 + threadIdx.x;
    if (i >= n) return;
    __nv_bfloat16 *hi = which ? g_wp_hi : g_wq_hi;
    __nv_bfloat16 *lo = which ? g_wp_lo : g_wq_lo;
    float v = src[i];
    __nv_bfloat16 h = __float2bfloat16(v);
    hi[i] = h;
    lo[i] = __float2bfloat16(v - __bfloat162float(h));
}

// ---------------- transpose-convert x[b][c][n] -> xT[(b,n)][c] hi/lo ----------------
__global__ void convT_x(const float* __restrict__ x)
{
    __shared__ float t[32][33];
    const int b  = blockIdx.z;
    const int n0 = blockIdx.x * 32;
    const int c0 = blockIdx.y * 32;
    const int tx = threadIdx.x, ty = threadIdx.y;
    #pragma unroll
    for (int i = 0; i < 4; i++)
        t[ty + i * 8][tx] = x[((size_t)b * CH + c0 + ty + i * 8) * SEQ + n0 + tx];
    __syncthreads();
    #pragma unroll
    for (int i = 0; i < 4; i++) {
        float v = t[tx][ty + i * 8];
        size_t idx = ((size_t)b * SEQ + n0 + ty + i * 8) * CH + c0 + tx;
        __nv_bfloat16 h = __float2bfloat16(v);
        g_xT_hi[idx] = h;
        g_xT_lo[idx] = __float2bfloat16(v - __bfloat162float(h));
    }
}

extern __shared__ unsigned char dynsmem[];

// ---------------------------------------------------------------------------
// Projection GEMMs: bf16x3 split, K-chunk 64, 3-stage cp.async ring,
// 512 threads, ldmx4-paired B fragments, ONE sync per chunk.
// SMEM: 3 stages x 4 arrays x (128 rows x 144 B) = 221184 B.
// ---------------------------------------------------------------------------
#define GST   144                 // row stride bytes (64 bf16 data + pad)
#define GARR  18432               // 128*144
#define GBUF  (4 * GARR)          // 73728 per stage
#define GSTG  3

template <int MODE>
__global__ void __launch_bounds__(512) gemm_mma(const float* __restrict__ bias,
                                                float* __restrict__ outp)
{
    constexpr int KDIM = 512;
    constexpr int NCHK = KDIM / 64;       // 8
    const int n0  = blockIdx.x * 128;
    const int m0  = blockIdx.y * 128;
    const int tid = threadIdx.x;
    const int w   = tid >> 5;
    const int lane = tid & 31;
    const int mw = (w & 3) * 32;
    const int nw = (w >> 2) * 32;

    const __nv_bfloat16 *Ahi, *Alo, *Bhi, *Blo;
    if (MODE == 0) { Ahi = g_xT_hi; Alo = g_xT_lo; Bhi = g_wq_hi; Blo = g_wq_lo; }
    else           { Ahi = g_wp_hi; Alo = g_wp_lo; Bhi = g_at_hi; Blo = g_at_lo; }

    const u32 sb = smem_u32(dynsmem);

    float acc[2][4][4];
    #pragma unroll
    for (int mf = 0; mf < 2; mf++)
        #pragma unroll
        for (int nf = 0; nf < 4; nf++)
            #pragma unroll
            for (int e = 0; e < 4; e++) acc[mf][nf][e] = 0.f;

    // A frag base: rows (mw + mf*16 + lane&15), k-half by lane>>4
    const u32 aOff = (u32)((mw + (lane & 15)) * GST + (lane >> 4) * 16);
    // B pair base: 4 lane-groups -> {rows +0..7 kh0, +0..7 kh1, +8..15 kh0, +8..15 kh1}
    const u32 bOffP = (u32)((nw + (lane & 7) + ((lane >> 4) & 1) * 8) * GST +
                            ((lane >> 3) & 1) * 16);

    const int lrow = tid >> 3, lc8 = tid & 7;   // with u: 1024 slots = 128 rows x 8 chunks

    auto issue = [&](int kc) {
        const int k0 = kc * 64;
        const u32 base = sb + (kc % GSTG) * GBUF;
        #pragma unroll
        for (int u = 0; u < 2; u++) {
            int row = lrow + u * 64;
            size_t srcA = (size_t)(m0 + row) * KDIM + k0 + lc8 * 8;
            size_t srcB = (size_t)(n0 + row) * KDIM + k0 + lc8 * 8;
            u32 d = base + (u32)(row * GST + lc8 * 16);
            cpa16(d,            Ahi + srcA);
            cpa16(d + GARR,     Alo + srcA);
            cpa16(d + 2 * GARR, Bhi + srcB);
            cpa16(d + 3 * GARR, Blo + srcB);
        }
        cp_commit();
    };

    issue(0); issue(1);
    for (int kc = 0; kc < NCHK; kc++) {
        cp_wait<1>();
        __syncthreads();

        const u32 base = sb + (kc % GSTG) * GBUF;
        #pragma unroll
        for (int ks = 0; ks < 4; ks++) {
            u32 ahi[2][4], alo[2][4];
            #pragma unroll
            for (int mf = 0; mf < 2; mf++) {
                ldmx4(base + aOff + mf * (16 * GST) + ks * 32, ahi[mf]);
                ldmx4(base + GARR + aOff + mf * (16 * GST) + ks * 32, alo[mf]);
            }
            #pragma unroll
            for (int nfp = 0; nfp < 2; nfp++) {
                u32 bh4[4], bl4[4];
                ldmx4(base + 2 * GARR + bOffP + nfp * (16 * GST) + ks * 32, bh4);
                ldmx4(base + 3 * GARR + bOffP + nfp * (16 * GST) + ks * 32, bl4);
                #pragma unroll
                for (int half = 0; half < 2; half++) {
                    const int nf = nfp * 2 + half;
                    #pragma unroll
                    for (int mf = 0; mf < 2; mf++) {
                        mma_bf16(acc[mf][nf], ahi[mf], &bh4[half * 2]);
                        mma_bf16(acc[mf][nf], ahi[mf], &bl4[half * 2]);
                        mma_bf16(acc[mf][nf], alo[mf], &bh4[half * 2]);
                    }
                }
            }
        }
        if (kc + 2 < NCHK) issue(kc + 2);
        else               cp_commit();
    }

    const int g  = lane >> 2;
    const int tg = lane & 3;
    #pragma unroll
    for (int mf = 0; mf < 2; mf++) {
        const int mA = m0 + mw + mf * 16 + g;
        const int mB = mA + 8;
        #pragma unroll
        for (int nf = 0; nf < 4; nf++) {
            const int nn = n0 + nw + nf * 8 + tg * 2;
            if (MODE == 0) {
                float2 bb = *(const float2*)&bias[nn];
                qkv_store(mA, nn, acc[mf][nf][0] + bb.x, acc[mf][nf][1] + bb.y);
                qkv_store(mB, nn, acc[mf][nf][2] + bb.x, acc[mf][nf][3] + bb.y);
            } else {
                const int bb_ = nn >> 10, np = nn & 1023;
                float biasA = bias[mA], biasB = bias[mB];
                float* ob = outp + (size_t)bb_ * CH * SEQ + np;
                *(float2*)&ob[(size_t)mA * SEQ] =
                    make_float2(acc[mf][nf][0] + biasA, acc[mf][nf][1] + biasA);
                *(float2*)&ob[(size_t)mB * SEQ] =
                    make_float2(acc[mf][nf][2] + biasB, acc[mf][nf][3] + biasB);
            }
        }
    }
}

// ---------------------------------------------------------------------------
// Fused flash attention with ldmx4-paired K and Vt fragments.
// grid (8 q-blocks reversed, 64 bh), 256 thr, 8 warps x 16 q-rows.
// SMEM: Q 2x18432 + 2 stages x (K 2x18432 + Vt 2x17408) = 180224 B.
// ---------------------------------------------------------------------------
#define QST2  144
#define QARR  18432
#define VST2  272
#define VARR  17408
#define STGSZ (2 * QARR + 2 * VARR)
#define SOFF  (2 * QARR)

__global__ void __launch_bounds__(256) attn_fused()
{
    const int r   = 7 - (int)blockIdx.x;
    const int bh  = blockIdx.y;
    const int b   = bh >> 3, h = bh & 7;
    const int tid = threadIdx.x;
    const int w   = tid >> 5;
    const int lane = tid & 31;
    const int g  = lane >> 2, tg = lane & 3;

    const __nv_bfloat16* Qhi = g_q_hi + ((size_t)bh << 16) + (size_t)r * 128 * HD;
    const __nv_bfloat16* Qlo = g_q_lo + ((size_t)bh << 16) + (size_t)r * 128 * HD;
    const __nv_bfloat16* Khi = g_k_hi + ((size_t)bh << 16);
    const __nv_bfloat16* Klo = g_k_lo + ((size_t)bh << 16);
    const __nv_bfloat16* Vhi = g_vt_hi + ((size_t)bh << 16);
    const __nv_bfloat16* Vlo = g_vt_lo + ((size_t)bh << 16);

    const u32 sb = smem_u32(dynsmem);

    // ---- load Q block (hi+lo) ----
    {
        #pragma unroll
        for (int u = 0; u < 4; u++) {
            int idx = u * 256 + tid;
            int row = idx >> 3, c8 = idx & 7;
            size_t src = (size_t)row * HD + c8 * 8;
            u32 d = sb + (u32)(row * QST2 + c8 * 16);
            cpa16(d,        Qhi + src);
            cpa16(d + QARR, Qlo + src);
        }
        cp_commit();
    }

    auto issueKV = [&](int c) {
        const u32 base = sb + SOFF + (c & 1) * STGSZ;
        #pragma unroll
        for (int u = 0; u < 4; u++) {
            int idx = u * 256 + tid;
            {   // K: 128 rows x 8 chunks
                int row = idx >> 3, c8 = idx & 7;
                size_t src = (size_t)(c * 128 + row) * HD + c8 * 8;
                u32 d = base + (u32)(row * QST2 + c8 * 16);
                cpa16(d,        Khi + src);
                cpa16(d + QARR, Klo + src);
            }
            {   // Vt: 64 rows x 16 chunks
                int row = idx >> 4, c16 = idx & 15;
                size_t src = (size_t)row * SEQ + c * 128 + c16 * 8;
                u32 d = base + 2 * QARR + (u32)(row * VST2 + c16 * 16);
                cpa16(d,        Vhi + src);
                cpa16(d + VARR, Vlo + src);
            }
        }
        cp_commit();
    };

    issueKV(0);
    cp_wait<1>();
    __syncthreads();

    // ---- Q fragments ----
    u32 qh[4][4], ql[4][4];
    {
        const u32 qa = sb + (u32)((w * 16 + (lane & 15)) * QST2 + (lane >> 4) * 16);
        #pragma unroll
        for (int ks = 0; ks < 4; ks++) {
            ldmx4(qa + ks * 32,        qh[ks]);
            ldmx4(qa + QARR + ks * 32, ql[ks]);
        }
    }

    if (r >= 1) issueKV(1);

    float o[8][4];
    #pragma unroll
    for (int nt = 0; nt < 8; nt++)
        #pragma unroll
        for (int e = 0; e < 4; e++) o[nt][e] = 0.f;
    float m0 = -1e30f, m1 = -1e30f, l0 = 0.f, l1 = 0.f;

    // K/V pair-fragment lane bases
    const u32 kOffP = (u32)(((lane & 7) + ((lane >> 4) & 1) * 8) * QST2 +
                            ((lane >> 3) & 1) * 16);
    const u32 vOffP = (u32)(((lane & 7) + ((lane >> 4) & 1) * 8) * VST2 +
                            ((lane >> 3) & 1) * 16);

    for (int c = 0; c <= r; c++) {
        if (c == r) cp_wait<0>(); else cp_wait<1>();
        __syncthreads();
        const u32 base = sb + SOFF + (c & 1) * STGSZ;

        // ---- S = Q K^T : ldmx4 pairs give two nt per load ----
        float s[16][4];
        #pragma unroll
        for (int nt = 0; nt < 16; nt++)
            #pragma unroll
            for (int e = 0; e < 4; e++) s[nt][e] = 0.f;

        #pragma unroll
        for (int ks = 0; ks < 4; ks++) {
            #pragma unroll
            for (int ntp = 0; ntp < 8; ntp++) {
                u32 kh4[4], kl4[4];
                u32 ka = base + kOffP + (u32)(ntp * 16 * QST2) + ks * 32;
                ldmx4(ka,        kh4);
                ldmx4(ka + QARR, kl4);
                mma_bf16(s[2*ntp],   qh[ks], &kh4[0]);
                mma_bf16(s[2*ntp],   qh[ks], &kl4[0]);
                mma_bf16(s[2*ntp],   ql[ks], &kh4[0]);
                mma_bf16(s[2*ntp+1], qh[ks], &kh4[2]);
                mma_bf16(s[2*ntp+1], qh[ks], &kl4[2]);
                mma_bf16(s[2*ntp+1], ql[ks], &kh4[2]);
            }
        }

        // ---- causal mask (diagonal block only) ----
        if (c == r) {
            const int i0 = w * 16 + g;
            const int i1 = i0 + 8;
            #pragma unroll
            for (int nt = 0; nt < 16; nt++) {
                const int j0 = nt * 8 + tg * 2;
                if (j0     > i0) s[nt][0] = -1e30f;
                if (j0 + 1 > i0) s[nt][1] = -1e30f;
                if (j0     > i1) s[nt][2] = -1e30f;
                if (j0 + 1 > i1) s[nt][3] = -1e30f;
            }
        }

        // ---- online softmax ----
        float mb0 = -1e30f, mb1 = -1e30f;
        #pragma unroll
        for (int nt = 0; nt < 16; nt++) {
            mb0 = fmaxf(mb0, fmaxf(s[nt][0], s[nt][1]));
            mb1 = fmaxf(mb1, fmaxf(s[nt][2], s[nt][3]));
        }
        mb0 = fmaxf(mb0, __shfl_xor_sync(0xffffffff, mb0, 1));
        mb0 = fmaxf(mb0, __shfl_xor_sync(0xffffffff, mb0, 2));
        mb1 = fmaxf(mb1, __shfl_xor_sync(0xffffffff, mb1, 1));
        mb1 = fmaxf(mb1, __shfl_xor_sync(0xffffffff, mb1, 2));

        const float mn0 = fmaxf(m0, mb0);
        const float mn1 = fmaxf(m1, mb1);
        const float a0 = __expf(m0 - mn0);
        const float a1 = __expf(m1 - mn1);
        l0 *= a0; l1 *= a1;
        #pragma unroll
        for (int nt = 0; nt < 8; nt++) {
            o[nt][0] *= a0; o[nt][1] *= a0;
            o[nt][2] *= a1; o[nt][3] *= a1;
        }
        float s0 = 0.f, s1 = 0.f;
        #pragma unroll
        for (int nt = 0; nt < 16; nt++) {
            s[nt][0] = __expf(s[nt][0] - mn0); s0 += s[nt][0];
            s[nt][1] = __expf(s[nt][1] - mn0); s0 += s[nt][1];
            s[nt][2] = __expf(s[nt][2] - mn1); s1 += s[nt][2];
            s[nt][3] = __expf(s[nt][3] - mn1); s1 += s[nt][3];
        }
        s0 += __shfl_xor_sync(0xffffffff, s0, 1);
        s0 += __shfl_xor_sync(0xffffffff, s0, 2);
        s1 += __shfl_xor_sync(0xffffffff, s1, 1);
        s1 += __shfl_xor_sync(0xffffffff, s1, 2);
        l0 += s0; l1 += s1;
        m0 = mn0; m1 = mn1;

        // ---- O += P V : ldmx4 pairs give two d-tiles per load ----
        #pragma unroll
        for (int kk = 0; kk < 8; kk++) {
            u32 ah[4], al[4];
            split_pack(s[2*kk][0],   s[2*kk][1],   ah[0], al[0]);
            split_pack(s[2*kk][2],   s[2*kk][3],   ah[1], al[1]);
            split_pack(s[2*kk+1][0], s[2*kk+1][1], ah[2], al[2]);
            split_pack(s[2*kk+1][2], s[2*kk+1][3], ah[3], al[3]);
            #pragma unroll
            for (int ntp = 0; ntp < 4; ntp++) {
                u32 vh4[4], vl4[4];
                u32 va = base + 2 * QARR + vOffP + (u32)(ntp * 16 * VST2) + kk * 32;
                ldmx4(va,        vh4);
                ldmx4(va + VARR, vl4);
                mma_bf16(o[2*ntp],   ah, &vh4[0]);
                mma_bf16(o[2*ntp],   ah, &vl4[0]);
                mma_bf16(o[2*ntp],   al, &vh4[0]);
                mma_bf16(o[2*ntp+1], ah, &vh4[2]);
                mma_bf16(o[2*ntp+1], ah, &vl4[2]);
                mma_bf16(o[2*ntp+1], al, &vh4[2]);
            }
        }

        __syncthreads();
        if (c + 2 <= r) issueKV(c + 2);
    }

    // ---- epilogue ----
    const float inv0 = 1.f / l0;
    const float inv1 = 1.f / l1;
    const int iA = r * 128 + w * 16 + g;
    const int iB = iA + 8;
    const size_t oA = ((size_t)(b * SEQ + iA)) * CH + h * HD;
    const size_t oB = ((size_t)(b * SEQ + iB)) * CH + h * HD;
    #pragma unroll
    for (int nt = 0; nt < 8; nt++) {
        const int dd = nt * 8 + tg * 2;
        store_split2(g_at_hi, g_at_lo, oA + dd, o[nt][0] * inv0, o[nt][1] * inv0);
        store_split2(g_at_hi, g_at_lo, oB + dd, o[nt][2] * inv1, o[nt][3] * inv1);
    }
}

// ---------------------------------------------------------------------------
extern "C" void kernel_launch(void* const* d_in, const int* in_sizes, int n_in,
                              void* d_out, int out_size)
{
    const float* x    = (const float*)d_in[0];
    const float* Wqkv = (const float*)d_in[1];
    const float* bqkv = (const float*)d_in[2];
    const float* Wp   = (const float*)d_in[3];
    const float* bp   = (const float*)d_in[4];
    float* out = (float*)d_out;
    (void)in_sizes; (void)n_in; (void)out_size;

    static int attr_done = 0;
    if (!attr_done) {
        cudaFuncSetAttribute(gemm_mma<0>, cudaFuncAttributeMaxDynamicSharedMemorySize, GSTG * GBUF);
        cudaFuncSetAttribute(gemm_mma<1>, cudaFuncAttributeMaxDynamicSharedMemorySize, GSTG * GBUF);
        cudaFuncSetAttribute(attn_fused,  cudaFuncAttributeMaxDynamicSharedMemorySize, SOFF + 2 * STGSZ);
        attr_done = 1;
    }

    conv_split<<<(QKV_DIM * CH + 255) / 256, 256>>>(0, Wqkv, QKV_DIM * CH);
    conv_split<<<(CH * CH + 255) / 256, 256>>>(1, Wp, CH * CH);
    convT_x<<<dim3(SEQ / 32, CH / 32, BATCH), dim3(32, 8)>>>(x);

    gemm_mma<0><<<dim3(QKV_DIM / 128, NTOK / 128), 512, GSTG * GBUF>>>(bqkv, out);  // -> q/k/vt splits

    attn_fused<<<dim3(8, NBH), 256, SOFF + 2 * STGSZ>>>();                          // -> g_at splits

    gemm_mma<1><<<dim3(NTOK / 128, CH / 128), 512, GSTG * GBUF>>>(bp, out);         // -> out
}